// round 8
// baseline (speedup 1.0000x reference)
#include <cuda_runtime.h>
#include <cstdint>

#define KTAGS 16
#define TLEN  512
#define BROWS 1024
#define START_ID 14
#define STOP_ID  15

__device__ float g_row_out[BROWS];
__device__ int   g_ctr = 0;      // last-block counter, self-resetting

typedef unsigned long long u64;

// ---- f32x2 packed helpers ----
__device__ __forceinline__ u64 pk2(float lo, float hi) {
    u64 r; asm("mov.b64 %0, {%1, %2};" : "=l"(r) : "f"(lo), "f"(hi)); return r;
}
__device__ __forceinline__ u64 mul2(u64 a, u64 b) {
    u64 r; asm("mul.rn.f32x2 %0, %1, %2;" : "=l"(r) : "l"(a), "l"(b)); return r;
}
__device__ __forceinline__ u64 fma2(u64 a, u64 b, u64 c) {
    u64 r; asm("fma.rn.f32x2 %0, %1, %2, %3;" : "=l"(r) : "l"(a), "l"(b), "l"(c)); return r;
}
__device__ __forceinline__ u64 add2(u64 a, u64 b) {
    u64 r; asm("add.rn.f32x2 %0, %1, %2;" : "=l"(r) : "l"(a), "l"(b)); return r;
}
__device__ __forceinline__ float hadd2(u64 a) {
    float lo, hi;
    asm("mov.b64 {%0, %1}, %2;" : "=f"(lo), "=f"(hi) : "l"(a));
    return lo + hi;
}

// ---------------------------------------------------------------------------
// Fused kernel. 128 threads = 8 groups of 16 lanes; one group per batch row.
// Forward recursion in linear domain: alpha_j = C + ln(p_j).
// Sync-free smem exchange: loop body is fully convergent (one PC per warp),
// so STS(t) precedes LDS(t) in the per-warp in-order smem pipeline;
// asm volatile + memory clobbers pin compiler ordering.
// Rotating emit pipeline: 1 MUFU + 1 LDG per step (no bursts).
// ---------------------------------------------------------------------------
__global__ void __launch_bounds__(128)
crf_fused_kernel(const float* __restrict__ h,
                 const int*   __restrict__ y32,      // raw y words (int32 view)
                 const float* __restrict__ mask,
                 const float* __restrict__ trans,
                 float* __restrict__ out) {
    __shared__ float tr_s[256];
    __shared__ __align__(16) float pbuf[2][8][16];   // [parity][group][state]
    __shared__ int   s_ysh;
    __shared__ int   s_last;
    __shared__ float s_red[4];

    const int tid = threadIdx.x;

    if (tid < 64) ((float4*)tr_s)[tid] = ((const float4*)trans)[tid];

    // y dtype detection: int64 layout -> hi 32-bit word of each u64 is 0.
    if (tid < 32) {
        u64 v = ((const u64*)y32)[(size_t)tid * 256];
        unsigned bal = __ballot_sync(0xFFFFFFFFu, (unsigned)(v >> 32) != 0u);
        if (tid == 0) s_ysh = (bal == 0u) ? 1 : 0;
    }
    __syncthreads();

    const int lane = tid & 15;
    const int gid  = tid >> 4;                  // 0..7 group in block
    const int row  = blockIdx.x * 8 + gid;
    const unsigned gmask = 0xFFFFu << ((gid & 1) * 16);

    const float* hrow = h    + (size_t)row * TLEN * KTAGS;
    const float* mrow = mask + (size_t)row * TLEN;
    const int ysh = s_ysh;
    const int* yrow = y32 + (((size_t)row * TLEN) << ysh);

    // smem exchange addresses (byte addresses into shared window)
    unsigned sb0, sb1, swr0, swr1;
    {
        unsigned base;
        asm("{ .reg .u64 t; cvta.to.shared.u64 t, %1; cvt.u32.u64 %0, t; }"
            : "=r"(base) : "l"(&pbuf[0][0][0]));
        sb0  = base + gid * 64;            // read base, parity 0
        sb1  = base + 512 + gid * 64;      // read base, parity 1
        swr0 = sb0 + lane * 4;             // write addr, parity 0
        swr1 = sb1 + lane * 4;
    }

    // Etr row of this lane, packed: Etr[i] = exp(trans[lane, i]).
    u64 EtrP[8];
#pragma unroll
    for (int k = 0; k < 8; k++)
        EtrP[k] = pk2(__expf(tr_s[lane * 16 + 2 * k]),
                      __expf(tr_s[lane * 16 + 2 * k + 1]));
    const float EtrStop = __expf(tr_s[STOP_ID * 16 + lane]);

    // ---- length + gold score (branchless, lane-parallel) ----
    float lsum = 0.f, gsum = 0.f;
#pragma unroll 4
    for (int k = lane; k < TLEN; k += 16) {
        float mk = mrow[k];
        int yt = yrow[k << ysh];
        int yp = (k == 0) ? START_ID : yrow[(k - 1) << ysh];
        lsum += mk;
        gsum = fmaf(mk, hrow[k * 16 + yt] + tr_s[yt * 16 + yp], gsum);
    }
#pragma unroll
    for (int s = 8; s; s >>= 1) {
        lsum += __shfl_xor_sync(gmask, lsum, s, 16);
        gsum += __shfl_xor_sync(gmask, gsum, s, 16);
    }
    const int len = (int)(lsum + 0.5f);
    const int lastTag = yrow[(len - 1) << ysh];
    const float gold = gsum + tr_s[STOP_ID * 16 + lastTag];

    // warp-uniform trip count: max over both groups, rounded up to 8
    int steps = (len + 7) & ~7;
    steps = max(steps, __shfl_xor_sync(0xFFFFFFFFu, steps, 16));

    // ---- forward recursion ----
    float p = (lane == START_ID) ? 1.0f : 0.0f;
    float C = 0.0f;

    // rotating pipelines: ehq = exp(emit) for steps t0..t0+7,
    //                     hb  = raw emit for steps t0+8..t0+15
    float ehq[8], hb[8];
#pragma unroll
    for (int d = 0; d < 8; d++) ehq[d] = __expf(hrow[d * 16 + lane]);
#pragma unroll
    for (int d = 0; d < 8; d++) hb[d] = hrow[(d + 8) * 16 + lane];

    for (int t0 = 0; t0 < steps; t0 += 8) {
        unsigned mu = 0u;       // stale-by-1 lane-local max of q bits (u==7)

#pragma unroll
        for (int u = 0; u < 8; u++) {
            const bool act = (t0 + u) < len;      // group-uniform -> FSEL
            const unsigned wr = (u & 1) ? swr1 : swr0;
            const unsigned rd = (u & 1) ? sb1 : sb0;

            asm volatile("st.shared.b32 [%0], %1;" :: "r"(wr), "f"(p) : "memory");

            float f0, f1, f2, f3, f4, f5, f6, f7;
            float f8, f9, f10, f11, f12, f13, f14, f15;
            asm volatile("ld.shared.v4.b32 {%0,%1,%2,%3}, [%4];"
                : "=f"(f0), "=f"(f1), "=f"(f2), "=f"(f3) : "r"(rd) : "memory");
            asm volatile("ld.shared.v4.b32 {%0,%1,%2,%3}, [%4];"
                : "=f"(f4), "=f"(f5), "=f"(f6), "=f"(f7) : "r"(rd + 16) : "memory");
            asm volatile("ld.shared.v4.b32 {%0,%1,%2,%3}, [%4];"
                : "=f"(f8), "=f"(f9), "=f"(f10), "=f"(f11) : "r"(rd + 32) : "memory");
            asm volatile("ld.shared.v4.b32 {%0,%1,%2,%3}, [%4];"
                : "=f"(f12), "=f"(f13), "=f"(f14), "=f"(f15) : "r"(rd + 48) : "memory");

            u64 q0 = pk2(f0,  f1),  q1 = pk2(f2,  f3);
            u64 q2 = pk2(f4,  f5),  q3 = pk2(f6,  f7);
            u64 q4 = pk2(f8,  f9),  q5 = pk2(f10, f11);
            u64 q6 = pk2(f12, f13), q7 = pk2(f14, f15);

            u64 a0 = fma2(q1, EtrP[1], mul2(q0, EtrP[0]));
            u64 a1 = fma2(q3, EtrP[3], mul2(q2, EtrP[2]));
            u64 a2 = fma2(q5, EtrP[5], mul2(q4, EtrP[4]));
            u64 a3 = fma2(q7, EtrP[7], mul2(q6, EtrP[6]));
            float S = hadd2(add2(add2(a0, a1), add2(a2, a3)));
            float pn = S * ehq[u];
            p = act ? pn : p;

            // rotate emit pipeline (off the dependency chain)
            ehq[u] = __expf(hb[u]);
            int idx = t0 + u + 16;
            idx = (idx > TLEN - 1) ? (TLEN - 1) : idx;
            hb[u] = hrow[idx * 16 + lane];

            if (u == 7) {
                unsigned m0 = max(__float_as_uint(f0),  __float_as_uint(f1));
                unsigned m1 = max(__float_as_uint(f2),  __float_as_uint(f3));
                unsigned m2 = max(__float_as_uint(f4),  __float_as_uint(f5));
                unsigned m3 = max(__float_as_uint(f6),  __float_as_uint(f7));
                unsigned m4 = max(__float_as_uint(f8),  __float_as_uint(f9));
                unsigned m5 = max(__float_as_uint(f10), __float_as_uint(f11));
                unsigned m6 = max(__float_as_uint(f12), __float_as_uint(f13));
                unsigned m7 = max(__float_as_uint(f14), __float_as_uint(f15));
                mu = max(max(max(m0, m1), max(m2, m3)),
                         max(max(m4, m5), max(m6, m7)));
            }
        }
        // exponent-only renorm: exact for any power-of-2 scale (invariant
        // alpha = C + ln p preserved, incl. frozen rows)
        int me = (int)(mu >> 23);
        me = (me < 1) ? 1 : me;
        float scale = __uint_as_float((unsigned)(254 - me) << 23);  // 2^(127-me)
        C += (float)(me - 127) * 0.6931471805599453f;
        p *= scale;
    }

    // fwd = C + ln( sum_j p_j * exp(trans[STOP, j]) )
    float v = p * EtrStop;
#pragma unroll
    for (int s = 8; s; s >>= 1)
        v += __shfl_xor_sync(gmask, v, s, 16);
    const float fwd = C + __logf(v);

    if (lane == 0) g_row_out[row] = fwd - gold;

    // ---- last-block mean reduction ----
    __threadfence();
    __syncthreads();
    if (tid == 0) {
        int old = atomicAdd(&g_ctr, 1);
        s_last = (old == gridDim.x - 1);
    }
    __syncthreads();
    if (s_last) {
        float s = 0.f;
#pragma unroll
        for (int i = 0; i < BROWS / 128; i++)
            s += g_row_out[tid + i * 128];
#pragma unroll
        for (int sft = 16; sft; sft >>= 1)
            s += __shfl_xor_sync(0xFFFFFFFFu, s, sft);
        if ((tid & 31) == 0) s_red[tid >> 5] = s;
        __syncthreads();
        if (tid == 0) {
            float tot = s_red[0] + s_red[1] + s_red[2] + s_red[3];
            out[0] = tot * (1.0f / (float)BROWS);
            g_ctr = 0;   // reset for next graph replay
        }
    }
}

// ---------------------------------------------------------------------------
extern "C" void kernel_launch(void* const* d_in, const int* in_sizes, int n_in,
                              void* d_out, int out_size) {
    const float* h     = (const float*)d_in[0];
    const int*   y     = (const int*)d_in[1];
    const float* mask  = (const float*)d_in[2];
    const float* trans = (const float*)d_in[3];
    float* out = (float*)d_out;

    crf_fused_kernel<<<BROWS / 8, 128>>>(h, y, mask, trans, out);
}